// round 5
// baseline (speedup 1.0000x reference)
#include <cuda_runtime.h>

#define HH 224
#define WW 224
#define BB 4
#define SS 21
#define RR 5
#define HW (HH*WW)

// Stage-1 intermediate: 84 shifted images, HWC pixels padded to float4.
// 84 * 50176 * 16B = 67.4 MB (static device scratch — allowed).
__device__ float4 g_x1[SS * BB * HW];

// cos/sin of ANGLES = {-0.5236, -0.2618, 0, 0.2618, 0.5236} (float64-accurate)
__constant__ float c_cos[RR] = {0.86602479158f, 0.96592566784f, 1.0f,
                                0.96592566784f, 0.86602479158f};
__constant__ float c_sin[RR] = {-0.50000106036f, -0.25881963644f, 0.0f,
                                 0.25881963644f,  0.50000106036f};

// ---------------------------------------------------------------------------
// Stage 1: axis-aligned half-pixel shifts with bilinear + zero padding.
// grid: (ceil(HW/256), S*B), block 256. One thread = one pixel of one image.
// ---------------------------------------------------------------------------
__global__ void __launch_bounds__(256) stage1_shift(const float* __restrict__ xs)
{
    int idx = blockIdx.x * 256 + threadIdx.x;
    if (idx >= HW) return;
    int n = blockIdx.y;          // 0..83 = s*B + b
    int s = n >> 2;
    int b = n & 3;
    int h = idx / WW;
    int w = idx - h * WW;

    // Shift table (order: up p=1..5, down p=1..5, left p=1..5, right p=1..5,0).
    // Normalized shift p/(W-1) == p/2 pixels.
    float dx = 0.f, dy = 0.f;
    if      (s < 5)  dy =  (float)(s + 1)  * 0.5f;
    else if (s < 10) dy = -(float)(s - 4)  * 0.5f;
    else if (s < 15) dx =  (float)(s - 9)  * 0.5f;
    else if (s < 20) dx = -(float)(s - 14) * 0.5f;
    // s == 20: identity

    float sx = (float)w + dx;
    float sy = (float)h + dy;
    float x0f = floorf(sx), y0f = floorf(sy);
    int   x0  = (int)x0f,   y0  = (int)y0f;
    float fx = sx - x0f, fy = sy - y0f;

    const float* img = xs + b * (HW * 3);
    float ax = 0.f, ay = 0.f, az = 0.f;
    #pragma unroll
    for (int j = 0; j < 2; j++) {
        int y = y0 + j;
        if ((unsigned)y >= HH) continue;
        float wy = j ? fy : (1.f - fy);
        #pragma unroll
        for (int i = 0; i < 2; i++) {
            int x = x0 + i;
            if ((unsigned)x >= WW) continue;
            float wgt = wy * (i ? fx : (1.f - fx));
            const float* p = img + (y * WW + x) * 3;
            ax += wgt * p[0];
            ay += wgt * p[1];
            az += wgt * p[2];
        }
    }
    g_x1[n * HW + idx] = make_float4(ax, ay, az, 0.f);
}

// ---------------------------------------------------------------------------
// Stage 2: rotation sampling of the shifted batch.
// grid: (ceil(HW/256), R*S*B), block 256. blockIdx.y = output image index m:
//   m = (r*S + s)*B + b  ->  r = m/84, x1 image n = m%84.
// ---------------------------------------------------------------------------
__global__ void __launch_bounds__(256) stage2_rotate(float* __restrict__ out)
{
    int idx = blockIdx.x * 256 + threadIdx.x;
    if (idx >= HW) return;
    int m = blockIdx.y;                 // 0..419
    int r = m / (SS * BB);
    int n = m - r * (SS * BB);          // x1 image index

    int h = idx / WW;
    int w = idx - h * WW;

    const float cx = 0.5f * (WW - 1);   // 111.5 (H == W)
    float u = (float)w - cx;
    float v = (float)h - cx;
    float cs = c_cos[r], sn = c_sin[r];
    float ix =  u * cs + v * sn + cx;
    float iy = -u * sn + v * cs + cx;

    float x0f = floorf(ix), y0f = floorf(iy);
    int   x0  = (int)x0f,   y0  = (int)y0f;
    float fx = ix - x0f, fy = iy - y0f;

    const float4* img = g_x1 + n * HW;
    float ax = 0.f, ay = 0.f, az = 0.f;
    #pragma unroll
    for (int j = 0; j < 2; j++) {
        int y = y0 + j;
        if ((unsigned)y >= HH) continue;
        float wy = j ? fy : (1.f - fy);
        #pragma unroll
        for (int i = 0; i < 2; i++) {
            int x = x0 + i;
            if ((unsigned)x >= WW) continue;
            float wgt = wy * (i ? fx : (1.f - fx));
            float4 pv = __ldg(img + y * WW + x);
            ax += wgt * pv.x;
            ay += wgt * pv.y;
            az += wgt * pv.z;
        }
    }

    int o = (m * HW + idx) * 3;
    out[o + 0] = ax;
    out[o + 1] = ay;
    out[o + 2] = az;
}

extern "C" void kernel_launch(void* const* d_in, const int* in_sizes, int n_in,
                              void* d_out, int out_size)
{
    (void)in_sizes; (void)n_in; (void)out_size;
    const float* xs = (const float*)d_in[0];
    float* out = (float*)d_out;

    dim3 blk(256);
    dim3 g1((HW + 255) / 256, SS * BB);        // (196, 84)
    dim3 g2((HW + 255) / 256, RR * SS * BB);   // (196, 420)

    stage1_shift<<<g1, blk>>>(xs);
    stage2_rotate<<<g2, blk>>>(out);
}